// round 6
// baseline (speedup 1.0000x reference)
#include <cuda_runtime.h>

#define CCH 256
#define CMID 16
#define HWSZ 16384
#define NGRP 32

// ---- device scratch (no allocations) ----
// g_dw: [(proj*2+input)][b][c][hw] proj:0=q,1=k,2=v. After K2 consumes q/k dw,
// region 0 (first 33554432 floats) is reused as U = alpha*V1@A1^T + beta*V2@A2^T.
__device__ float g_dw[201326592];
__device__ float g_q[4194304];      // [input][b][m][hw]
__device__ float g_k[4194304];
__device__ float g_fused[33554432]; // [b][c][hw]
__device__ float g_psum[131072];    // [b][g][hwtile][2]
__device__ float2 g_stats[256];     // [b][g]

// ---- tf32 helpers ----
__device__ __forceinline__ unsigned f2tf(float f)
{ unsigned r; asm("cvt.rna.tf32.f32 %0, %1;" : "=r"(r) : "f"(f)); return r; }

__device__ __forceinline__ void mma_tf32(float d[4], const unsigned a[4], const unsigned bb[2])
{
    asm volatile("mma.sync.aligned.m16n8k8.row.col.f32.tf32.tf32.f32 "
        "{%0,%1,%2,%3},{%4,%5,%6,%7},{%8,%9},{%0,%1,%2,%3};"
        : "+f"(d[0]),"+f"(d[1]),"+f"(d[2]),"+f"(d[3])
        : "r"(a[0]),"r"(a[1]),"r"(a[2]),"r"(a[3]),"r"(bb[0]),"r"(bb[1]));
}

// ---- K1: fused depthwise 3x3 (q,k,v) on both inputs ----
__global__ __launch_bounds__(256) void dw_kernel(
    const float* __restrict__ img, const float* __restrict__ mask,
    const float* __restrict__ qw, const float* __restrict__ qb,
    const float* __restrict__ kw, const float* __restrict__ kb,
    const float* __restrict__ vw, const float* __restrict__ vb)
{
    int bid = blockIdx.x;
    int band = bid & 15;
    int bc = (bid >> 4) & 2047;
    int input = bid >> 15;
    int c = bc & 255;
    const float* src = (input ? mask : img) + (size_t)bc * HWSZ;

    __shared__ float s[10 * 132];
    int t = threadIdx.x;
    int y0 = band * 8;
    for (int i = t; i < 10 * 130; i += 256) {
        int r = i / 130, cc = i - r * 130;
        int gy = y0 - 1 + r, gx = cc - 1;
        float v = 0.f;
        if ((unsigned)gy < 128u && (unsigned)gx < 128u) v = src[gy * 128 + gx];
        s[r * 132 + cc] = v;
    }
    float wq[9], wk[9], wv[9];
#pragma unroll
    for (int j = 0; j < 9; j++) { wq[j]=qw[c*9+j]; wk[j]=kw[c*9+j]; wv[j]=vw[c*9+j]; }
    float bq = qb[c], bk = kb[c], bv = vb[c];
    __syncthreads();

    int x = t & 127, quad = t >> 7;
    float aq[4], ak[4], av[4];
#pragma unroll
    for (int r = 0; r < 4; r++) { aq[r]=bq; ak[r]=bk; av[r]=bv; }
#pragma unroll
    for (int dx = 0; dx < 3; dx++) {
        float col[6];
#pragma unroll
        for (int rr = 0; rr < 6; rr++) col[rr] = s[(quad*4+rr)*132 + x + dx];
#pragma unroll
        for (int r = 0; r < 4; r++)
#pragma unroll
            for (int dy = 0; dy < 3; dy++) {
                float v = col[r + dy]; int j = dy*3 + dx;
                aq[r] += wq[j]*v; ak[r] += wk[j]*v; av[r] += wv[j]*v;
            }
    }
    float* dq = g_dw + ((size_t)(0 + input)*2048 + bc)*(size_t)HWSZ;
    float* dk = g_dw + ((size_t)(2 + input)*2048 + bc)*(size_t)HWSZ;
    float* dv = g_dw + ((size_t)(4 + input)*2048 + bc)*(size_t)HWSZ;
#pragma unroll
    for (int r = 0; r < 4; r++) {
        int y = y0 + quad*4 + r;
        dq[y*128 + x] = aq[r]; dk[y*128 + x] = ak[r]; dv[y*128 + x] = av[r];
    }
}

// ---- K2: q/k pointwise (16x256 per pixel) ----
__global__ __launch_bounds__(256) void pwqk_kernel(
    const float* __restrict__ qpw_w, const float* __restrict__ qpw_b,
    const float* __restrict__ kpw_w, const float* __restrict__ kpw_b)
{
    int which = blockIdx.y;
    int input = which & 1, proj = which >> 1;
    const float* Wp = proj ? kpw_w : qpw_w;
    const float* bp = proj ? kpw_b : qpw_b;
    const float* dwb = g_dw + (size_t)(proj*2 + input)*2048*(size_t)HWSZ;
    float* outb = (proj ? g_k : g_q) + (size_t)input*8*CMID*HWSZ;

    __shared__ float4 ws[CMID*64];
    __shared__ float  bs[CMID];
    int t = threadIdx.x;
    for (int i = t; i < CMID*64; i += 256) ws[i] = ((const float4*)Wp)[i];
    if (t < CMID) bs[t] = bp[t];
    __syncthreads();

    int n = blockIdx.x*256 + t;
    int b = n >> 14, hw = n & 16383;
    const float* xp = dwb + ((size_t)b*CCH)*HWSZ + hw;
    float acc[CMID];
#pragma unroll
    for (int m = 0; m < CMID; m++) acc[m] = bs[m];
#pragma unroll 4
    for (int c4 = 0; c4 < 64; c4++) {
        float x0 = xp[(size_t)(4*c4+0)*HWSZ];
        float x1 = xp[(size_t)(4*c4+1)*HWSZ];
        float x2 = xp[(size_t)(4*c4+2)*HWSZ];
        float x3 = xp[(size_t)(4*c4+3)*HWSZ];
#pragma unroll
        for (int m = 0; m < CMID; m++) {
            float4 w = ws[m*64 + c4];
            acc[m] += w.x*x0 + w.y*x1 + w.z*x2 + w.w*x3;
        }
    }
    float* op = outb + ((size_t)b*CMID)*HWSZ + hw;
#pragma unroll
    for (int m = 0; m < CMID; m++) op[(size_t)m*HWSZ] = acc[m];
}

// ---- K3 helpers ----
#define ST_STRIDE 72
#define VT_STRIDE 264

__device__ __forceinline__ void qk_gemm(const float* sQ, const float* sK, float* sSt, int t)
{
    int tx = t & 15, ty = t >> 4;
    int q0 = tx*4, p0 = ty*4;
    float a[4][4];
#pragma unroll
    for (int i=0;i<4;i++)
#pragma unroll
        for (int j=0;j<4;j++) a[i][j]=0.f;
#pragma unroll
    for (int c = 0; c < 16; c++) {
        float4 kk = *(const float4*)&sK[c*64 + q0];
        float4 qq = *(const float4*)&sQ[c*64 + p0];
        float kr[4]={kk.x,kk.y,kk.z,kk.w}, qr[4]={qq.x,qq.y,qq.z,qq.w};
#pragma unroll
        for (int i=0;i<4;i++)
#pragma unroll
            for (int j=0;j<4;j++) a[i][j] += kr[i]*qr[j];
    }
#pragma unroll
    for (int i=0;i<4;i++)
#pragma unroll
        for (int j=0;j<4;j++) sSt[(q0+i)*ST_STRIDE + p0+j] = 0.25f*a[i][j];
}

// 256-thread softmax over columns; writes back tf32 bit patterns (scaled)
__device__ __forceinline__ void softmax_tf32(float* sSt, int t, float scale)
{
    int p = t >> 2, qt = t & 3;
    float* col = sSt + p;
    float mx = -1e30f;
#pragma unroll
    for (int i = 0; i < 16; i++) mx = fmaxf(mx, col[(qt*16 + i)*ST_STRIDE]);
    mx = fmaxf(mx, __shfl_xor_sync(0xffffffffu, mx, 1));
    mx = fmaxf(mx, __shfl_xor_sync(0xffffffffu, mx, 2));
    float e[16], sum = 0.f;
#pragma unroll
    for (int i = 0; i < 16; i++) {
        e[i] = __expf(col[(qt*16 + i)*ST_STRIDE] - mx);
        sum += e[i];
    }
    sum += __shfl_xor_sync(0xffffffffu, sum, 1);
    sum += __shfl_xor_sync(0xffffffffu, sum, 2);
    float inv = scale / sum;
#pragma unroll
    for (int i = 0; i < 16; i++)
        col[(qt*16 + i)*ST_STRIDE] = __uint_as_float(f2tf(e[i]*inv));
}

// PV via tensor cores: d[c-tile][p-tile] += V[c,q] * A[p,q]
__device__ __forceinline__ void pv_mma(float d[4][4][4], const unsigned* sVt,
                                       const unsigned* sStu, int warpM, int warpN, int lane)
{
#pragma unroll
    for (int ks = 0; ks < 8; ks++) {
        int ar = ks*8 + (lane & 3), am = lane >> 2;
        unsigned a[4][4], bb[4][2];
#pragma unroll
        for (int i = 0; i < 4; i++) {
            int mi = warpM*64 + i*16 + am;
            a[i][0] = sVt[ar*VT_STRIDE + mi];       a[i][1] = sVt[ar*VT_STRIDE + mi + 8];
            a[i][2] = sVt[(ar+4)*VT_STRIDE + mi];   a[i][3] = sVt[(ar+4)*VT_STRIDE + mi + 8];
        }
#pragma unroll
        for (int j = 0; j < 4; j++) {
            int nj = warpN*32 + j*8 + am;
            bb[j][0] = sStu[ar*ST_STRIDE + nj];
            bb[j][1] = sStu[(ar+4)*ST_STRIDE + nj];
        }
#pragma unroll
        for (int i = 0; i < 4; i++)
#pragma unroll
            for (int j = 0; j < 4; j++) mma_tf32(d[i][j], a[i], bb[j]);
    }
}

// smem (u32): sQ 0(1024) sK 1024(1024) St1 2048(4608) St2 6656(4608) sVt 11264(16896)
#define ATTN_SMEM_FLOATS 28160

// ---- K3: attention both directions, writes U = alpha*V1@A1^T + beta*V2@A2^T ----
__global__ __launch_bounds__(256, 1) void attn_kernel(
    const float* __restrict__ alpha_p, const float* __restrict__ beta_p)
{
    extern __shared__ float sm[];
    float* sQ   = sm;
    float* sK   = sm + 1024;
    float* sSt1 = sm + 2048;
    float* sSt2 = sm + 6656;
    unsigned* sVt = (unsigned*)(sm + 11264);

    int t = threadIdx.x, lane = t & 31, warp = t >> 5;
    int warpM = warp >> 1, warpN = warp & 1;
    int bid = blockIdx.x;
    int b = bid >> 8, blkid = bid & 255;
    int by = blkid >> 4, bx = blkid & 15;
    float al = __ldg(alpha_p), be = __ldg(beta_p);
    int hw00 = by*8*128 + bx*8;

    {   // dir1: Q=mask, K=img
        const float* qs = g_q + (((size_t)8 + b)*CMID)*HWSZ;
        const float* ks = g_k + (((size_t)0 + b)*CMID)*HWSZ;
        for (int e = t; e < 1024; e += 256) {
            int m = e >> 6, p = e & 63;
            int hw = hw00 + ((p>>3)<<7) + (p&7);
            sQ[m*64+p] = qs[(size_t)m*HWSZ + hw];
            sK[m*64+p] = ks[(size_t)m*HWSZ + hw];
        }
    }
    __syncthreads();
    qk_gemm(sQ, sK, sSt1, t);
    __syncthreads();
    {   // dir2 load + softmax(St1, alpha)
        const float* qs = g_q + (((size_t)0 + b)*CMID)*HWSZ;
        const float* ks = g_k + (((size_t)8 + b)*CMID)*HWSZ;
        for (int e = t; e < 1024; e += 256) {
            int m = e >> 6, p = e & 63;
            int hw = hw00 + ((p>>3)<<7) + (p&7);
            sQ[m*64+p] = qs[(size_t)m*HWSZ + hw];
            sK[m*64+p] = ks[(size_t)m*HWSZ + hw];
        }
        softmax_tf32(sSt1, t, al);
    }
    __syncthreads();
    qk_gemm(sQ, sK, sSt2, t);
    {   // load V1 = dwv(img), transposed K-major, tf32
        const float* vs = g_dw + (((size_t)4*8 + b)*CCH)*(size_t)HWSZ;
        int q = t & 63, cb = t >> 6;
        int hw = hw00 + ((q>>3)<<7) + (q&7);
#pragma unroll 4
        for (int cc = 0; cc < 64; cc++) {
            int c = cc*4 + cb;
            sVt[q*VT_STRIDE + c] = f2tf(vs[(size_t)c*HWSZ + hw]);
        }
    }
    __syncthreads();
    softmax_tf32(sSt2, t, be);

    float d[4][4][4];
#pragma unroll
    for (int i=0;i<4;i++)
#pragma unroll
        for (int j=0;j<4;j++)
#pragma unroll
            for (int e=0;e<4;e++) d[i][j][e]=0.f;

    pv_mma(d, sVt, (const unsigned*)sSt1, warpM, warpN, lane);
    __syncthreads();
    {   // load V2 = dwv(mask)
        const float* vs = g_dw + (((size_t)5*8 + b)*CCH)*(size_t)HWSZ;
        int q = t & 63, cb = t >> 6;
        int hw = hw00 + ((q>>3)<<7) + (q&7);
#pragma unroll 4
        for (int cc = 0; cc < 64; cc++) {
            int c = cc*4 + cb;
            sVt[q*VT_STRIDE + c] = f2tf(vs[(size_t)c*HWSZ + hw]);
        }
    }
    __syncthreads();
    pv_mma(d, sVt, (const unsigned*)sSt2, warpM, warpN, lane);

    // store U to g_dw region 0, layout [b][c][hw]
    size_t ub = ((size_t)b*CCH) << 14;
#pragma unroll
    for (int i = 0; i < 4; i++) {
#pragma unroll
        for (int half = 0; half < 2; half++) {
            int c = warpM*64 + i*16 + (lane>>2) + half*8;
#pragma unroll
            for (int j = 0; j < 4; j++) {
                int p = warpN*32 + j*8 + (lane&3)*2;
                int hw = hw00 + ((p>>3)<<7) + (p&7);
                *(float2*)&g_dw[ub + ((size_t)c<<14) + hw] =
                    make_float2(d[i][j][half*2], d[i][j][half*2+1]);
            }
        }
    }
}

// ---- K4: tf32 GEMM: fused = Wv x U + ab*bv + img + mask, GN partials ----
#define GEMM_SMEM_BYTES 69632

__global__ __launch_bounds__(256, 1) void gemm_kernel(
    const float* __restrict__ Wv, const float* __restrict__ bvp,
    const float* __restrict__ img, const float* __restrict__ mask,
    const float* __restrict__ alpha_p, const float* __restrict__ beta_p)
{
    extern __shared__ unsigned sg[];
    unsigned* sAb[2] = { sg, sg + 4352 };
    unsigned* sBb[2] = { sg + 8704, sg + 13056 };

    const int t = threadIdx.x, lane = t & 31, warp = t >> 5;
    const int warpM = warp >> 2, warpN = warp & 3;
    const int hwt = blockIdx.x, mt = blockIdx.y, b = blockIdx.z;
    const int n0 = hwt * 128;
    const float* U = g_dw;

    float d[4][4][4];
#pragma unroll
    for (int i=0;i<4;i++)
#pragma unroll
        for (int j=0;j<4;j++)
#pragma unroll
            for (int e=0;e<4;e++) d[i][j][e]=0.f;

    {
#pragma unroll
        for (int s = 0; s < 4; s++) {
            int fid = s*256 + t;
            { int row = fid >> 3, c4 = fid & 7;
              float4 v = *(const float4*)&Wv[(size_t)(mt*128+row)*256 + c4*4];
              int ba = (c4*4)*136 + row;
              sAb[0][ba]=f2tf(v.x); sAb[0][ba+136]=f2tf(v.y);
              sAb[0][ba+272]=f2tf(v.z); sAb[0][ba+408]=f2tf(v.w); }
            { int kr = fid >> 5, cc = (fid & 31)*4;
              float4 v = *(const float4*)&U[((size_t)(b*256+kr) << 14) + n0 + cc];
              int ba = kr*136 + cc;
              sBb[0][ba]=f2tf(v.x); sBb[0][ba+1]=f2tf(v.y);
              sBb[0][ba+2]=f2tf(v.z); sBb[0][ba+3]=f2tf(v.w); }
        }
    }
    __syncthreads();

    float4 ra[4], rb[4];
    for (int kt = 0; kt < 8; kt++) {
        int cur = kt & 1;
        if (kt < 7) {
            int kc = (kt+1)*32;
#pragma unroll
            for (int s = 0; s < 4; s++) {
                int fid = s*256 + t;
                int row = fid >> 3, c4 = fid & 7;
                ra[s] = *(const float4*)&Wv[(size_t)(mt*128+row)*256 + kc + c4*4];
                int kr = fid >> 5, cc = (fid & 31)*4;
                rb[s] = *(const float4*)&U[((size_t)(b*256+kc+kr) << 14) + n0 + cc];
            }
        }
        const unsigned* sA = sAb[cur];
        const unsigned* sB = sBb[cur];
#pragma unroll
        for (int ks = 0; ks < 4; ks++) {
            int kb = ks*8;
            int ar = kb + (lane & 3), am = lane >> 2;
            unsigned a[4][4], bb[4][2];
#pragma unroll
            for (int i = 0; i < 4; i++) {
                int mi = warpM*64 + i*16 + am;
                a[i][0] = sA[ar*136 + mi];      a[i][1] = sA[ar*136 + mi + 8];
                a[i][2] = sA[(ar+4)*136 + mi];  a[i][3] = sA[(ar+4)*136 + mi + 8];
            }
#pragma unroll
            for (int j = 0; j < 4; j++) {
                int nj = warpN*32 + j*8 + am;
                bb[j][0] = sB[ar*136 + nj];
                bb[j][1] = sB[(ar+4)*136 + nj];
            }
#pragma unroll
            for (int i = 0; i < 4; i++)
#pragma unroll
                for (int j = 0; j < 4; j++) mma_tf32(d[i][j], a[i], bb[j]);
        }
        if (kt < 7) {
            int nxt = cur ^ 1;
#pragma unroll
            for (int s = 0; s < 4; s++) {
                int fid = s*256 + t;
                int row = fid >> 3, c4 = fid & 7;
                int ba = (c4*4)*136 + row;
                sAb[nxt][ba]=f2tf(ra[s].x); sAb[nxt][ba+136]=f2tf(ra[s].y);
                sAb[nxt][ba+272]=f2tf(ra[s].z); sAb[nxt][ba+408]=f2tf(ra[s].w);
                int kr = fid >> 5, cc = (fid & 31)*4;
                int bbase = kr*136 + cc;
                sBb[nxt][bbase]=f2tf(rb[s].x); sBb[nxt][bbase+1]=f2tf(rb[s].y);
                sBb[nxt][bbase+2]=f2tf(rb[s].z); sBb[nxt][bbase+3]=f2tf(rb[s].w);
            }
            __syncthreads();
        }
    }
    __syncthreads();

    float* stage = (float*)sg;   // 128 x 129
    float ab = __ldg(alpha_p) + __ldg(beta_p);
    int r = lane >> 2, cc = (lane & 3)*2;
#pragma unroll
    for (int i = 0; i < 4; i++) {
#pragma unroll
        for (int half = 0; half < 2; half++) {
            int ro = warpM*64 + i*16 + r + half*8;
            int o = mt*128 + ro;
            float bias = ab * __ldg(&bvp[o]);
#pragma unroll
            for (int j = 0; j < 4; j++) {
                int nl = warpN*32 + j*8 + cc;
                size_t g = ((size_t)(b*256 + o) << 14) + n0 + nl;
                float2 iv = *(const float2*)&img[g];
                float2 mv = *(const float2*)&mask[g];
                float v0 = d[i][j][half*2+0] + bias + iv.x + mv.x;
                float v1 = d[i][j][half*2+1] + bias + iv.y + mv.y;
                *(float2*)&g_fused[g] = make_float2(v0, v1);
                stage[ro*129 + nl]     = v0;
                stage[ro*129 + nl + 1] = v1;
            }
        }
    }
    __syncthreads();

    int row = t >> 1, hf = t & 1;
    float s = 0.f, q = 0.f;
#pragma unroll 8
    for (int x = 0; x < 64; x++) {
        float v = stage[row*129 + hf*64 + x];
        s += v; q += v*v;
    }
    s += __shfl_xor_sync(0xffffffffu, s, 1);
    q += __shfl_xor_sync(0xffffffffu, q, 1);
    __shared__ float rs[128], rq[128];
    if (!hf) { rs[row] = s; rq[row] = q; }
    __syncthreads();
    if (t < 16) {
        float ss = 0.f, qq = 0.f;
#pragma unroll
        for (int k = 0; k < 8; k++) { ss += rs[t*8+k]; qq += rq[t*8+k]; }
        int g = mt*16 + t;
        int idx = ((b*32 + g)*128 + hwt)*2;
        g_psum[idx] = ss; g_psum[idx+1] = qq;
    }
}

// ---- K5: reduce GN partials ----
__global__ __launch_bounds__(128) void stats_kernel()
{
    int bg = blockIdx.x, t = threadIdx.x;
    float2 v = ((const float2*)g_psum)[bg*128 + t];
    float s = v.x, q = v.y;
#pragma unroll
    for (int o = 16; o; o >>= 1) {
        s += __shfl_xor_sync(0xffffffffu, s, o);
        q += __shfl_xor_sync(0xffffffffu, q, o);
    }
    __shared__ float ss[4], qs[4];
    if ((t & 31) == 0) { ss[t>>5] = s; qs[t>>5] = q; }
    __syncthreads();
    if (t == 0) {
        for (int w = 1; w < 4; w++) { s += ss[w]; q += qs[w]; }
        float inv = 1.f / 131072.f;
        float mu = s * inv;
        float var = q * inv - mu*mu;
        g_stats[bg] = make_float2(mu, rsqrtf(var + 1e-5f));
    }
}

// ---- K6: normalize ----
__global__ __launch_bounds__(1024) void norm_kernel(
    float* __restrict__ out, const float* __restrict__ gamma, const float* __restrict__ beta)
{
    int i4 = blockIdx.x*1024 + threadIdx.x;
    size_t e = (size_t)i4 << 2;
    int b = (int)(e >> 22), c = (int)(e >> 14) & 255;
    float2 st = g_stats[b*32 + (c >> 3)];
    float gsc = gamma[c] * st.y;
    float bsh = beta[c] - st.x * gsc;
    float4 f = *(const float4*)&g_fused[e];
    float4 r;
    r.x = f.x*gsc + bsh; r.y = f.y*gsc + bsh;
    r.z = f.z*gsc + bsh; r.w = f.w*gsc + bsh;
    *(float4*)&out[e] = r;
}

extern "C" void kernel_launch(void* const* d_in, const int* in_sizes, int n_in,
                              void* d_out, int out_size)
{
    const float* img    = (const float*)d_in[0];
    const float* mask   = (const float*)d_in[1];
    const float* qdw_w  = (const float*)d_in[2];
    const float* qdw_b  = (const float*)d_in[3];
    const float* kdw_w  = (const float*)d_in[4];
    const float* kdw_b  = (const float*)d_in[5];
    const float* vdw_w  = (const float*)d_in[6];
    const float* vdw_b  = (const float*)d_in[7];
    const float* qpw_w  = (const float*)d_in[8];
    const float* qpw_b  = (const float*)d_in[9];
    const float* kpw_w  = (const float*)d_in[10];
    const float* kpw_b  = (const float*)d_in[11];
    const float* vpw_w  = (const float*)d_in[12];
    const float* vpw_b  = (const float*)d_in[13];
    const float* alpha  = (const float*)d_in[14];
    const float* beta   = (const float*)d_in[15];
    const float* gn_w   = (const float*)d_in[16];
    const float* gn_b   = (const float*)d_in[17];

    cudaFuncSetAttribute(attn_kernel, cudaFuncAttributeMaxDynamicSharedMemorySize,
                         ATTN_SMEM_FLOATS * 4);
    cudaFuncSetAttribute(gemm_kernel, cudaFuncAttributeMaxDynamicSharedMemorySize,
                         GEMM_SMEM_BYTES);

    dw_kernel<<<65536, 256>>>(img, mask, qdw_w, qdw_b, kdw_w, kdw_b, vdw_w, vdw_b);
    dim3 g2(512, 4);
    pwqk_kernel<<<g2, 256>>>(qpw_w, qpw_b, kpw_w, kpw_b);
    attn_kernel<<<2048, 256, ATTN_SMEM_FLOATS * 4>>>(alpha, beta);
    dim3 g4(128, 2, 8);
    gemm_kernel<<<g4, 256, GEMM_SMEM_BYTES>>>(vpw_w, vpw_b, img, mask, alpha, beta);
    stats_kernel<<<256, 128>>>();
    norm_kernel<<<8192, 1024>>>((float*)d_out, gn_w, gn_b);
}

// round 7
// speedup vs baseline: 1.0959x; 1.0959x over previous
#include <cuda_runtime.h>

#define CCH 256
#define CMID 16
#define HWSZ 16384
#define NGRP 32

// ---- device scratch (no allocations) ----
// g_dw: [(proj*2+input)][b][c][hw] proj:0=q,1=k,2=v. After K2 consumes q/k dw,
// region 0 (first 33554432 floats) is reused as U = alpha*V1@A1^T + beta*V2@A2^T.
__device__ float g_dw[201326592];
__device__ float g_q[4194304];      // [input][b][m][hw]
__device__ float g_k[4194304];
__device__ float g_fused[33554432]; // [b][c][hw]
__device__ float g_psum[131072];    // [b][g][hwtile][2]
__device__ float2 g_stats[256];     // [b][g]

__device__ __forceinline__ void mma_tf32(float d[4], const unsigned a[4], const unsigned bb[2])
{
    asm volatile("mma.sync.aligned.m16n8k8.row.col.f32.tf32.tf32.f32 "
        "{%0,%1,%2,%3},{%4,%5,%6,%7},{%8,%9},{%0,%1,%2,%3};"
        : "+f"(d[0]),"+f"(d[1]),"+f"(d[2]),"+f"(d[3])
        : "r"(a[0]),"r"(a[1]),"r"(a[2]),"r"(a[3]),"r"(bb[0]),"r"(bb[1]));
}

// ---- K1: fused depthwise 3x3 (q,k,v) on both inputs ----
__global__ __launch_bounds__(256) void dw_kernel(
    const float* __restrict__ img, const float* __restrict__ mask,
    const float* __restrict__ qw, const float* __restrict__ qb,
    const float* __restrict__ kw, const float* __restrict__ kb,
    const float* __restrict__ vw, const float* __restrict__ vb)
{
    int bid = blockIdx.x;
    int band = bid & 15;
    int bc = (bid >> 4) & 2047;
    int input = bid >> 15;
    int c = bc & 255;
    const float* src = (input ? mask : img) + (size_t)bc * HWSZ;

    __shared__ float s[10 * 132];
    int t = threadIdx.x;
    int y0 = band * 8;
    for (int i = t; i < 10 * 130; i += 256) {
        int r = i / 130, cc = i - r * 130;
        int gy = y0 - 1 + r, gx = cc - 1;
        float v = 0.f;
        if ((unsigned)gy < 128u && (unsigned)gx < 128u) v = src[gy * 128 + gx];
        s[r * 132 + cc] = v;
    }
    float wq[9], wk[9], wv[9];
#pragma unroll
    for (int j = 0; j < 9; j++) { wq[j]=qw[c*9+j]; wk[j]=kw[c*9+j]; wv[j]=vw[c*9+j]; }
    float bq = qb[c], bk = kb[c], bv = vb[c];
    __syncthreads();

    int x = t & 127, quad = t >> 7;
    float aq[4], ak[4], av[4];
#pragma unroll
    for (int r = 0; r < 4; r++) { aq[r]=bq; ak[r]=bk; av[r]=bv; }
#pragma unroll
    for (int dx = 0; dx < 3; dx++) {
        float col[6];
#pragma unroll
        for (int rr = 0; rr < 6; rr++) col[rr] = s[(quad*4+rr)*132 + x + dx];
#pragma unroll
        for (int r = 0; r < 4; r++)
#pragma unroll
            for (int dy = 0; dy < 3; dy++) {
                float v = col[r + dy]; int j = dy*3 + dx;
                aq[r] += wq[j]*v; ak[r] += wk[j]*v; av[r] += wv[j]*v;
            }
    }
    float* dq = g_dw + ((size_t)(0 + input)*2048 + bc)*(size_t)HWSZ;
    float* dk = g_dw + ((size_t)(2 + input)*2048 + bc)*(size_t)HWSZ;
    float* dv = g_dw + ((size_t)(4 + input)*2048 + bc)*(size_t)HWSZ;
#pragma unroll
    for (int r = 0; r < 4; r++) {
        int y = y0 + quad*4 + r;
        dq[y*128 + x] = aq[r]; dk[y*128 + x] = ak[r]; dv[y*128 + x] = av[r];
    }
}

// ---- K2: q/k pointwise (16x256 per pixel) ----
__global__ __launch_bounds__(256) void pwqk_kernel(
    const float* __restrict__ qpw_w, const float* __restrict__ qpw_b,
    const float* __restrict__ kpw_w, const float* __restrict__ kpw_b)
{
    int which = blockIdx.y;
    int input = which & 1, proj = which >> 1;
    const float* Wp = proj ? kpw_w : qpw_w;
    const float* bp = proj ? kpw_b : qpw_b;
    const float* dwb = g_dw + (size_t)(proj*2 + input)*2048*(size_t)HWSZ;
    float* outb = (proj ? g_k : g_q) + (size_t)input*8*CMID*HWSZ;

    __shared__ float4 ws[CMID*64];
    __shared__ float  bs[CMID];
    int t = threadIdx.x;
    for (int i = t; i < CMID*64; i += 256) ws[i] = ((const float4*)Wp)[i];
    if (t < CMID) bs[t] = bp[t];
    __syncthreads();

    int n = blockIdx.x*256 + t;
    int b = n >> 14, hw = n & 16383;
    const float* xp = dwb + ((size_t)b*CCH)*HWSZ + hw;
    float acc[CMID];
#pragma unroll
    for (int m = 0; m < CMID; m++) acc[m] = bs[m];
#pragma unroll 4
    for (int c4 = 0; c4 < 64; c4++) {
        float x0 = xp[(size_t)(4*c4+0)*HWSZ];
        float x1 = xp[(size_t)(4*c4+1)*HWSZ];
        float x2 = xp[(size_t)(4*c4+2)*HWSZ];
        float x3 = xp[(size_t)(4*c4+3)*HWSZ];
#pragma unroll
        for (int m = 0; m < CMID; m++) {
            float4 w = ws[m*64 + c4];
            acc[m] += w.x*x0 + w.y*x1 + w.z*x2 + w.w*x3;
        }
    }
    float* op = outb + ((size_t)b*CMID)*HWSZ + hw;
#pragma unroll
    for (int m = 0; m < CMID; m++) op[(size_t)m*HWSZ] = acc[m];
}

// ---- K3 helpers (fp32 PV path — known good from R5) ----
__device__ __forceinline__ void qk_gemm(const float* sQ, const float* sK, float* sSt, int t)
{
    int tx = t & 15, ty = t >> 4;
    int q0 = tx*4, p0 = ty*4;
    float a[4][4];
#pragma unroll
    for (int i=0;i<4;i++)
#pragma unroll
        for (int j=0;j<4;j++) a[i][j]=0.f;
#pragma unroll
    for (int c = 0; c < 16; c++) {
        float4 kk = *(const float4*)&sK[c*64 + q0];
        float4 qq = *(const float4*)&sQ[c*64 + p0];
        float kr[4]={kk.x,kk.y,kk.z,kk.w}, qr[4]={qq.x,qq.y,qq.z,qq.w};
#pragma unroll
        for (int i=0;i<4;i++)
#pragma unroll
            for (int j=0;j<4;j++) a[i][j] += kr[i]*qr[j];
    }
#pragma unroll
    for (int i=0;i<4;i++)
#pragma unroll
        for (int j=0;j<4;j++) sSt[(q0+i)*68 + p0+j] = 0.25f*a[i][j];
}

__device__ __forceinline__ void softmax_col(float* sSt, int p, float scale)
{
    float mx = -1e30f;
    for (int q = 0; q < 64; q++) mx = fmaxf(mx, sSt[q*68+p]);
    float sum = 0.f;
    for (int q = 0; q < 64; q++) { float e = __expf(sSt[q*68+p]-mx); sSt[q*68+p]=e; sum+=e; }
    float inv = scale / sum;
    for (int q = 0; q < 64; q++) sSt[q*68+p] *= inv;
}

__device__ __forceinline__ void t_accum(float acc[8][8], const float* sV, const float* sSt,
                                        int c0, int p0)
{
#pragma unroll 2
    for (int q = 0; q < 64; q++) {
        float av[8];
#pragma unroll
        for (int i=0;i<8;i++) av[i] = sV[(c0+i)*65 + q];
        float4 u0 = *(const float4*)&sSt[q*68 + p0];
        float4 u1 = *(const float4*)&sSt[q*68 + p0 + 4];
        float uu[8]={u0.x,u0.y,u0.z,u0.w,u1.x,u1.y,u1.z,u1.w};
#pragma unroll
        for (int i=0;i<8;i++)
#pragma unroll
            for (int j=0;j<8;j++) acc[i][j] += av[i]*uu[j];
    }
}

// smem (floats): Q 0..1024, K 1024..2048, St1 2048(4352), St2 6400(4352), V 10752(16640)
#define ATTN_SMEM_FLOATS 27392

// ---- K3: attention both directions, writes U = alpha*V1@A1^T + beta*V2@A2^T ----
__global__ __launch_bounds__(256, 1) void attn_kernel(
    const float* __restrict__ alpha_p, const float* __restrict__ beta_p)
{
    extern __shared__ float sm[];
    float* sQ   = sm;
    float* sK   = sm + 1024;
    float* sSt1 = sm + 2048;
    float* sSt2 = sm + 6400;
    float* sV   = sm + 10752;

    int t = threadIdx.x;
    int bid = blockIdx.x;
    int b = bid >> 8, blkid = bid & 255;
    int by = blkid >> 4, bx = blkid & 15;
    float al = __ldg(alpha_p), be = __ldg(beta_p);
    int hw00 = by*8*128 + bx*8;

    {   // dir1: Q=mask, K=img
        const float* qs = g_q + (((size_t)8 + b)*CMID)*HWSZ;
        const float* ks = g_k + (((size_t)0 + b)*CMID)*HWSZ;
        for (int e = t; e < 1024; e += 256) {
            int m = e >> 6, p = e & 63;
            int hw = hw00 + ((p>>3)<<7) + (p&7);
            sQ[m*64+p] = qs[(size_t)m*HWSZ + hw];
            sK[m*64+p] = ks[(size_t)m*HWSZ + hw];
        }
    }
    __syncthreads();
    qk_gemm(sQ, sK, sSt1, t);
    __syncthreads();
    {   // dir2 load + softmax(St1, alpha)
        const float* qs = g_q + (((size_t)0 + b)*CMID)*HWSZ;
        const float* ks = g_k + (((size_t)8 + b)*CMID)*HWSZ;
        for (int e = t; e < 1024; e += 256) {
            int m = e >> 6, p = e & 63;
            int hw = hw00 + ((p>>3)<<7) + (p&7);
            sQ[m*64+p] = qs[(size_t)m*HWSZ + hw];
            sK[m*64+p] = ks[(size_t)m*HWSZ + hw];
        }
        if (t < 64) softmax_col(sSt1, t, al);
    }
    __syncthreads();
    qk_gemm(sQ, sK, sSt2, t);
    __syncthreads();
    {   // load dwv(img) + softmax(St2, beta)
        const float* vs = g_dw + (((size_t)4*8 + b)*CCH)*(size_t)HWSZ;
        for (int e = t; e < 256*64; e += 256) {
            int c = e >> 6, q = e & 63;
            int hw = hw00 + ((q>>3)<<7) + (q&7);
            sV[c*65+q] = vs[(size_t)c*HWSZ + hw];
        }
        if (t < 64) softmax_col(sSt2, t, be);
    }
    __syncthreads();

    int pg = t & 7, cg = t >> 3;
    int c0 = cg*8, p0 = pg*8;
    float acc[8][8];
#pragma unroll
    for (int i=0;i<8;i++)
#pragma unroll
        for (int j=0;j<8;j++) acc[i][j]=0.f;

    t_accum(acc, sV, sSt1, c0, p0);
    __syncthreads();
    {
        const float* vs = g_dw + (((size_t)5*8 + b)*CCH)*(size_t)HWSZ;
        for (int e = t; e < 256*64; e += 256) {
            int c = e >> 6, q = e & 63;
            int hw = hw00 + ((q>>3)<<7) + (q&7);
            sV[c*65+q] = vs[(size_t)c*HWSZ + hw];
        }
    }
    __syncthreads();
    t_accum(acc, sV, sSt2, c0, p0);

    // write U to g_dw region 0 (layout [b][c][hw])
    size_t ub0 = (((size_t)b*CCH + c0) << 14) + (size_t)hw00 + ((size_t)pg << 7);
#pragma unroll
    for (int i = 0; i < 8; i++) {
        size_t ga = ub0 + ((size_t)i << 14);
        *(float4*)&g_dw[ga]   = make_float4(acc[i][0],acc[i][1],acc[i][2],acc[i][3]);
        *(float4*)&g_dw[ga+4] = make_float4(acc[i][4],acc[i][5],acc[i][6],acc[i][7]);
    }
}

// ---- K4: tf32 GEMM with fragment-order smem ----
// smem: sAf[2][1024] uint4 (32KB) + sBf[2][2048] uint2 (32KB) = 65536 B mainloop;
// epilogue stage 128x129 f32 = 66048 B. Total allocation 66048.
#define GEMM_SMEM_BYTES 66048

__global__ __launch_bounds__(256, 1) void gemm_kernel(
    const float* __restrict__ Wv, const float* __restrict__ bvp,
    const float* __restrict__ img, const float* __restrict__ mask,
    const float* __restrict__ alpha_p, const float* __restrict__ beta_p)
{
    extern __shared__ unsigned sg[];
    uint4* sAf = (uint4*)sg;               // [2][1024]
    uint2* sBf = (uint2*)(sg + 8192);      // [2][2048]

    const int t = threadIdx.x, lane = t & 31, warp = t >> 5;
    const int warpM = warp >> 2, warpN = warp & 3;
    const int hwt = blockIdx.x, mt = blockIdx.y, b = blockIdx.z;
    const int n0 = hwt * 128;
    const float* U = g_dw;

    float d[4][4][4];
#pragma unroll
    for (int i=0;i<4;i++)
#pragma unroll
        for (int j=0;j<4;j++)
#pragma unroll
            for (int e=0;e<4;e++) d[i][j][e]=0.f;

    // A fragment entry e: lane=e&31, fr=e>>5 = ((ks*2+wM)*4+i)
    //   m = mt*128 + wM*64 + i*16 + (lane>>2), k = kc + ks*8 + (lane&3)
    //   holds {A[m][k], A[m+8][k], A[m][k+4], A[m+8][k+4]}  (raw f32 bits as tf32)
    // B fragment entry e: lane=e&31, fr=e>>5 = ((ks*4+wN)*4+j)
    //   n = n0 + wN*32 + j*8 + (lane>>2), k = kc + ks*8 + (lane&3)
    //   holds {B[k][n], B[k+4][n]}

    {   // prologue: slab 0 -> buffer 0
        int kc = 0;
#pragma unroll
        for (int s = 0; s < 4; s++) {
            int e = s*256 + t;
            int le = e & 31, fr = e >> 5;
            int ks = fr >> 3, wM = (fr >> 2) & 1, i = fr & 3;
            int m = mt*128 + wM*64 + i*16 + (le>>2);
            int k = kc + ks*8 + (le&3);
            const float* wp = &Wv[(size_t)m*256 + k];
            sAf[e] = make_uint4(__float_as_uint(wp[0]),
                                __float_as_uint(wp[8*256]),
                                __float_as_uint(wp[4]),
                                __float_as_uint(wp[8*256+4]));
        }
#pragma unroll
        for (int s = 0; s < 8; s++) {
            int e = s*256 + t;
            int le = e & 31, fr = e >> 5;
            int ks = fr >> 4, wN = (fr >> 2) & 3, j = fr & 3;
            int n = n0 + wN*32 + j*8 + (le>>2);
            int k = kc + ks*8 + (le&3);
            const float* up = &U[((size_t)(b*256 + k) << 14) + n];
            sBf[e] = make_uint2(__float_as_uint(up[0]),
                                __float_as_uint(up[4 << 14]));
        }
    }
    __syncthreads();

    uint4 ra[4]; uint2 rb[8];
    for (int kt = 0; kt < 8; kt++) {
        int cur = kt & 1;
        if (kt < 7) {
            int kc = (kt+1)*32;
#pragma unroll
            for (int s = 0; s < 4; s++) {
                int e = s*256 + t;
                int le = e & 31, fr = e >> 5;
                int ks = fr >> 3, wM = (fr >> 2) & 1, i = fr & 3;
                int m = mt*128 + wM*64 + i*16 + (le>>2);
                int k = kc + ks*8 + (le&3);
                const float* wp = &Wv[(size_t)m*256 + k];
                ra[s] = make_uint4(__float_as_uint(wp[0]),
                                   __float_as_uint(wp[8*256]),
                                   __float_as_uint(wp[4]),
                                   __float_as_uint(wp[8*256+4]));
            }
#pragma unroll
            for (int s = 0; s < 8; s++) {
                int e = s*256 + t;
                int le = e & 31, fr = e >> 5;
                int ks = fr >> 4, wN = (fr >> 2) & 3, j = fr & 3;
                int n = n0 + wN*32 + j*8 + (le>>2);
                int k = kc + ks*8 + (le&3);
                const float* up = &U[((size_t)(b*256 + k) << 14) + n];
                rb[s] = make_uint2(__float_as_uint(up[0]),
                                   __float_as_uint(up[4 << 14]));
            }
        }
        const uint4* sA = sAf + cur*1024;
        const uint2* sB = sBf + cur*2048;
#pragma unroll
        for (int ks = 0; ks < 4; ks++) {
            uint4 av[4]; uint2 bv[4];
#pragma unroll
            for (int i = 0; i < 4; i++)
                av[i] = sA[((ks*2 + warpM)*4 + i)*32 + lane];
#pragma unroll
            for (int j = 0; j < 4; j++)
                bv[j] = sB[((ks*4 + warpN)*4 + j)*32 + lane];
#pragma unroll
            for (int i = 0; i < 4; i++) {
                unsigned a[4] = {av[i].x, av[i].y, av[i].z, av[i].w};
#pragma unroll
                for (int j = 0; j < 4; j++) {
                    unsigned bb[2] = {bv[j].x, bv[j].y};
                    mma_tf32(d[i][j], a, bb);
                }
            }
        }
        if (kt < 7) {
            int nxt = cur ^ 1;
            __syncthreads();
#pragma unroll
            for (int s = 0; s < 4; s++) sAf[nxt*1024 + s*256 + t] = ra[s];
#pragma unroll
            for (int s = 0; s < 8; s++) sBf[nxt*2048 + s*256 + t] = rb[s];
            __syncthreads();
        }
    }
    __syncthreads();   // done with fragments; reuse smem as epilogue staging

    float* stage = (float*)sg;   // 128 x 129
    float ab = __ldg(alpha_p) + __ldg(beta_p);
    int r = lane >> 2, cc = (lane & 3)*2;
#pragma unroll
    for (int i = 0; i < 4; i++) {
#pragma unroll
        for (int half = 0; half < 2; half++) {
            int ro = warpM*64 + i*16 + r + half*8;
            int o = mt*128 + ro;
            float bias = ab * __ldg(&bvp[o]);
#pragma unroll
            for (int j = 0; j < 4; j++) {
                int nl = warpN*32 + j*8 + cc;
                size_t g = ((size_t)(b*256 + o) << 14) + n0 + nl;
                float2 iv = *(const float2*)&img[g];
                float2 mv = *(const float2*)&mask[g];
                float v0 = d[i][j][half*2+0] + bias + iv.x + mv.x;
                float v1 = d[i][j][half*2+1] + bias + iv.y + mv.y;
                *(float2*)&g_fused[g] = make_float2(v0, v1);
                stage[ro*129 + nl]     = v0;
                stage[ro*129 + nl + 1] = v1;
            }
        }
    }
    __syncthreads();

    int row = t >> 1, hf = t & 1;
    float s = 0.f, q = 0.f;
#pragma unroll 8
    for (int x = 0; x < 64; x++) {
        float v = stage[row*129 + hf*64 + x];
        s += v; q += v*v;
    }
    s += __shfl_xor_sync(0xffffffffu, s, 1);
    q += __shfl_xor_sync(0xffffffffu, q, 1);
    __shared__ float rs[128], rq[128];
    if (!hf) { rs[row] = s; rq[row] = q; }
    __syncthreads();
    if (t < 16) {
        float ss = 0.f, qq = 0.f;
#pragma unroll
        for (int k = 0; k < 8; k++) { ss += rs[t*8+k]; qq += rq[t*8+k]; }
        int g = mt*16 + t;
        int idx = ((b*32 + g)*128 + hwt)*2;
        g_psum[idx] = ss; g_psum[idx+1] = qq;
    }
}

// ---- K5: reduce GN partials ----
__global__ __launch_bounds__(128) void stats_kernel()
{
    int bg = blockIdx.x, t = threadIdx.x;
    float2 v = ((const float2*)g_psum)[bg*128 + t];
    float s = v.x, q = v.y;
#pragma unroll
    for (int o = 16; o; o >>= 1) {
        s += __shfl_xor_sync(0xffffffffu, s, o);
        q += __shfl_xor_sync(0xffffffffu, q, o);
    }
    __shared__ float ss[4], qs[4];
    if ((t & 31) == 0) { ss[t>>5] = s; qs[t>>5] = q; }
    __syncthreads();
    if (t == 0) {
        for (int w = 1; w < 4; w++) { s += ss[w]; q += qs[w]; }
        float inv = 1.f / 131072.f;
        float mu = s * inv;
        float var = q * inv - mu*mu;
        g_stats[bg] = make_float2(mu, rsqrtf(var + 1e-5f));
    }
}

// ---- K6: normalize ----
__global__ __launch_bounds__(1024) void norm_kernel(
    float* __restrict__ out, const float* __restrict__ gamma, const float* __restrict__ beta)
{
    int i4 = blockIdx.x*1024 + threadIdx.x;
    size_t e = (size_t)i4 << 2;
    int b = (int)(e >> 22), c = (int)(e >> 14) & 255;
    float2 st = g_stats[b*32 + (c >> 3)];
    float gsc = gamma[c] * st.y;
    float bsh = beta[c] - st.x * gsc;
    float4 f = *(const float4*)&g_fused[e];
    float4 r;
    r.x = f.x*gsc + bsh; r.y = f.y*gsc + bsh;
    r.z = f.z*gsc + bsh; r.w = f.w*gsc + bsh;
    *(float4*)&out[e] = r;
}

extern "C" void kernel_launch(void* const* d_in, const int* in_sizes, int n_in,
                              void* d_out, int out_size)
{
    const float* img    = (const float*)d_in[0];
    const float* mask   = (const float*)d_in[1];
    const float* qdw_w  = (const float*)d_in[2];
    const float* qdw_b  = (const float*)d_in[3];
    const float* kdw_w  = (const float*)d_in[4];
    const float* kdw_b  = (const float*)d_in[5];
    const float* vdw_w  = (const float*)d_in[6];
    const float* vdw_b  = (const float*)d_in[7];
    const float* qpw_w  = (const float*)d_in[8];
    const float* qpw_b  = (const float*)d_in[9];
    const float* kpw_w  = (const float*)d_in[10];
    const float* kpw_b  = (const float*)d_in[11];
    const float* vpw_w  = (const float*)d_in[12];
    const float* vpw_b  = (const float*)d_in[13];
    const float* alpha  = (const float*)d_in[14];
    const float* beta   = (const float*)d_in[15];
    const float* gn_w   = (const float*)d_in[16];
    const float* gn_b   = (const float*)d_in[17];

    cudaFuncSetAttribute(attn_kernel, cudaFuncAttributeMaxDynamicSharedMemorySize,
                         ATTN_SMEM_FLOATS * 4);
    cudaFuncSetAttribute(gemm_kernel, cudaFuncAttributeMaxDynamicSharedMemorySize,
                         GEMM_SMEM_BYTES);

    dw_kernel<<<65536, 256>>>(img, mask, qdw_w, qdw_b, kdw_w, kdw_b, vdw_w, vdw_b);
    dim3 g2(512, 4);
    pwqk_kernel<<<g2, 256>>>(qpw_w, qpw_b, kpw_w, kpw_b);
    attn_kernel<<<2048, 256, ATTN_SMEM_FLOATS * 4>>>(alpha, beta);
    dim3 g4(128, 2, 8);
    gemm_kernel<<<g4, 256, GEMM_SMEM_BYTES>>>(vpw_w, vpw_b, img, mask, alpha, beta);
    stats_kernel<<<256, 128>>>();
    norm_kernel<<<8192, 1024>>>((float*)d_out, gn_w, gn_b);
}

// round 8
// speedup vs baseline: 1.1505x; 1.0498x over previous
#include <cuda_runtime.h>

#define CCH 256
#define CMID 16
#define HWSZ 16384
#define NGRP 32

// ---- device scratch (no allocations) ----
__device__ float g_dw[201326592];   // [(proj*2+input)][b][c][hw]; region 0 reused as U
__device__ float g_q[4194304];      // [input][b][m][hw]
__device__ float g_k[4194304];
__device__ float g_fused[33554432]; // [b][c][hw]
__device__ float g_psum[131072];    // [b][g][hwtile][2]
__device__ float2 g_stats[256];     // [b][g]

__device__ __forceinline__ void mma_tf32(float d[4], const unsigned a[4], const unsigned bb[2])
{
    asm volatile("mma.sync.aligned.m16n8k8.row.col.f32.tf32.tf32.f32 "
        "{%0,%1,%2,%3},{%4,%5,%6,%7},{%8,%9},{%0,%1,%2,%3};"
        : "+f"(d[0]),"+f"(d[1]),"+f"(d[2]),"+f"(d[3])
        : "r"(a[0]),"r"(a[1]),"r"(a[2]),"r"(a[3]),"r"(bb[0]),"r"(bb[1]));
}

// ---- K1: fused depthwise 3x3 (q,k,v) on both inputs ----
__global__ __launch_bounds__(256) void dw_kernel(
    const float* __restrict__ img, const float* __restrict__ mask,
    const float* __restrict__ qw, const float* __restrict__ qb,
    const float* __restrict__ kw, const float* __restrict__ kb,
    const float* __restrict__ vw, const float* __restrict__ vb)
{
    int bid = blockIdx.x;
    int band = bid & 15;
    int bc = (bid >> 4) & 2047;
    int input = bid >> 15;
    int c = bc & 255;
    const float* src = (input ? mask : img) + (size_t)bc * HWSZ;

    __shared__ float s[10 * 132];
    int t = threadIdx.x;
    int y0 = band * 8;
    for (int i = t; i < 10 * 130; i += 256) {
        int r = i / 130, cc = i - r * 130;
        int gy = y0 - 1 + r, gx = cc - 1;
        float v = 0.f;
        if ((unsigned)gy < 128u && (unsigned)gx < 128u) v = src[gy * 128 + gx];
        s[r * 132 + cc] = v;
    }
    float wq[9], wk[9], wv[9];
#pragma unroll
    for (int j = 0; j < 9; j++) { wq[j]=qw[c*9+j]; wk[j]=kw[c*9+j]; wv[j]=vw[c*9+j]; }
    float bq = qb[c], bk = kb[c], bv = vb[c];
    __syncthreads();

    int x = t & 127, quad = t >> 7;
    float aq[4], ak[4], av[4];
#pragma unroll
    for (int r = 0; r < 4; r++) { aq[r]=bq; ak[r]=bk; av[r]=bv; }
#pragma unroll
    for (int dx = 0; dx < 3; dx++) {
        float col[6];
#pragma unroll
        for (int rr = 0; rr < 6; rr++) col[rr] = s[(quad*4+rr)*132 + x + dx];
#pragma unroll
        for (int r = 0; r < 4; r++)
#pragma unroll
            for (int dy = 0; dy < 3; dy++) {
                float v = col[r + dy]; int j = dy*3 + dx;
                aq[r] += wq[j]*v; ak[r] += wk[j]*v; av[r] += wv[j]*v;
            }
    }
    float* dq = g_dw + ((size_t)(0 + input)*2048 + bc)*(size_t)HWSZ;
    float* dk = g_dw + ((size_t)(2 + input)*2048 + bc)*(size_t)HWSZ;
    float* dv = g_dw + ((size_t)(4 + input)*2048 + bc)*(size_t)HWSZ;
#pragma unroll
    for (int r = 0; r < 4; r++) {
        int y = y0 + quad*4 + r;
        dq[y*128 + x] = aq[r]; dk[y*128 + x] = ak[r]; dv[y*128 + x] = av[r];
    }
}

// ---- K2: q/k pointwise (16x256 per pixel) ----
__global__ __launch_bounds__(256) void pwqk_kernel(
    const float* __restrict__ qpw_w, const float* __restrict__ qpw_b,
    const float* __restrict__ kpw_w, const float* __restrict__ kpw_b)
{
    int which = blockIdx.y;
    int input = which & 1, proj = which >> 1;
    const float* Wp = proj ? kpw_w : qpw_w;
    const float* bp = proj ? kpw_b : qpw_b;
    const float* dwb = g_dw + (size_t)(proj*2 + input)*2048*(size_t)HWSZ;
    float* outb = (proj ? g_k : g_q) + (size_t)input*8*CMID*HWSZ;

    __shared__ float4 ws[CMID*64];
    __shared__ float  bs[CMID];
    int t = threadIdx.x;
    for (int i = t; i < CMID*64; i += 256) ws[i] = ((const float4*)Wp)[i];
    if (t < CMID) bs[t] = bp[t];
    __syncthreads();

    int n = blockIdx.x*256 + t;
    int b = n >> 14, hw = n & 16383;
    const float* xp = dwb + ((size_t)b*CCH)*HWSZ + hw;
    float acc[CMID];
#pragma unroll
    for (int m = 0; m < CMID; m++) acc[m] = bs[m];
#pragma unroll 4
    for (int c4 = 0; c4 < 64; c4++) {
        float x0 = xp[(size_t)(4*c4+0)*HWSZ];
        float x1 = xp[(size_t)(4*c4+1)*HWSZ];
        float x2 = xp[(size_t)(4*c4+2)*HWSZ];
        float x3 = xp[(size_t)(4*c4+3)*HWSZ];
#pragma unroll
        for (int m = 0; m < CMID; m++) {
            float4 w = ws[m*64 + c4];
            acc[m] += w.x*x0 + w.y*x1 + w.z*x2 + w.w*x3;
        }
    }
    float* op = outb + ((size_t)b*CMID)*HWSZ + hw;
#pragma unroll
    for (int m = 0; m < CMID; m++) op[(size_t)m*HWSZ] = acc[m];
}

// ---- K3 helpers ----
__device__ __forceinline__ void qk_gemm(const float* sQ, const float* sK, float* sSt, int t)
{
    int tx = t & 15, ty = t >> 4;
    int q0 = tx*4, p0 = ty*4;
    float a[4][4];
#pragma unroll
    for (int i=0;i<4;i++)
#pragma unroll
        for (int j=0;j<4;j++) a[i][j]=0.f;
#pragma unroll
    for (int c = 0; c < 16; c++) {
        float4 kk = *(const float4*)&sK[c*64 + q0];
        float4 qq = *(const float4*)&sQ[c*64 + p0];
        float kr[4]={kk.x,kk.y,kk.z,kk.w}, qr[4]={qq.x,qq.y,qq.z,qq.w};
#pragma unroll
        for (int i=0;i<4;i++)
#pragma unroll
            for (int j=0;j<4;j++) a[i][j] += kr[i]*qr[j];
    }
#pragma unroll
    for (int i=0;i<4;i++)
#pragma unroll
        for (int j=0;j<4;j++) sSt[(q0+i)*68 + p0+j] = 0.25f*a[i][j];
}

__device__ __forceinline__ void softmax_col(float* sSt, int p, float scale)
{
    float mx = -1e30f;
    for (int q = 0; q < 64; q++) mx = fmaxf(mx, sSt[q*68+p]);
    float sum = 0.f;
    for (int q = 0; q < 64; q++) { float e = __expf(sSt[q*68+p]-mx); sSt[q*68+p]=e; sum+=e; }
    float inv = scale / sum;
    for (int q = 0; q < 64; q++) sSt[q*68+p] *= inv;
}

__device__ __forceinline__ void t_accum(float acc[8][8], const float* sV, const float* sSt,
                                        int c0, int p0)
{
#pragma unroll 2
    for (int q = 0; q < 64; q++) {
        float av[8];
#pragma unroll
        for (int i=0;i<8;i++) av[i] = sV[(c0+i)*65 + q];
        float4 u0 = *(const float4*)&sSt[q*68 + p0];
        float4 u1 = *(const float4*)&sSt[q*68 + p0 + 4];
        float uu[8]={u0.x,u0.y,u0.z,u0.w,u1.x,u1.y,u1.z,u1.w};
#pragma unroll
        for (int i=0;i<8;i++)
#pragma unroll
            for (int j=0;j<8;j++) acc[i][j] += av[i]*uu[j];
    }
}

// smem (floats): Q 0..1024, K 1024..2048, St1 2048(4352), St2 6400(4352), V 10752(16640)
#define ATTN_SMEM_FLOATS 27392

// ---- K3: attention both directions, writes U ----
__global__ __launch_bounds__(256, 2) void attn_kernel(
    const float* __restrict__ alpha_p, const float* __restrict__ beta_p)
{
    extern __shared__ float sm[];
    float* sQ   = sm;
    float* sK   = sm + 1024;
    float* sSt1 = sm + 2048;
    float* sSt2 = sm + 6400;
    float* sV   = sm + 10752;

    int t = threadIdx.x;
    int bid = blockIdx.x;
    int b = bid >> 8, blkid = bid & 255;
    int by = blkid >> 4, bx = blkid & 15;
    float al = __ldg(alpha_p), be = __ldg(beta_p);
    int hw00 = by*8*128 + bx*8;

    {   // dir1: Q=mask, K=img
        const float* qs = g_q + (((size_t)8 + b)*CMID)*HWSZ;
        const float* ks = g_k + (((size_t)0 + b)*CMID)*HWSZ;
        for (int e = t; e < 1024; e += 256) {
            int m = e >> 6, p = e & 63;
            int hw = hw00 + ((p>>3)<<7) + (p&7);
            sQ[m*64+p] = qs[(size_t)m*HWSZ + hw];
            sK[m*64+p] = ks[(size_t)m*HWSZ + hw];
        }
    }
    __syncthreads();
    qk_gemm(sQ, sK, sSt1, t);
    __syncthreads();
    {   // dir2 load + softmax(St1, alpha)
        const float* qs = g_q + (((size_t)0 + b)*CMID)*HWSZ;
        const float* ks = g_k + (((size_t)8 + b)*CMID)*HWSZ;
        for (int e = t; e < 1024; e += 256) {
            int m = e >> 6, p = e & 63;
            int hw = hw00 + ((p>>3)<<7) + (p&7);
            sQ[m*64+p] = qs[(size_t)m*HWSZ + hw];
            sK[m*64+p] = ks[(size_t)m*HWSZ + hw];
        }
        if (t < 64) softmax_col(sSt1, t, al);
    }
    __syncthreads();
    qk_gemm(sQ, sK, sSt2, t);
    __syncthreads();
    {   // load dwv(img) + softmax(St2, beta)
        const float* vs = g_dw + (((size_t)4*8 + b)*CCH)*(size_t)HWSZ;
        for (int e = t; e < 256*64; e += 256) {
            int c = e >> 6, q = e & 63;
            int hw = hw00 + ((q>>3)<<7) + (q&7);
            sV[c*65+q] = vs[(size_t)c*HWSZ + hw];
        }
        if (t < 64) softmax_col(sSt2, t, be);
    }
    __syncthreads();

    int pg = t & 7, cg = t >> 3;
    int c0 = cg*8, p0 = pg*8;
    float acc[8][8];
#pragma unroll
    for (int i=0;i<8;i++)
#pragma unroll
        for (int j=0;j<8;j++) acc[i][j]=0.f;

    t_accum(acc, sV, sSt1, c0, p0);
    __syncthreads();
    {
        const float* vs = g_dw + (((size_t)5*8 + b)*CCH)*(size_t)HWSZ;
        for (int e = t; e < 256*64; e += 256) {
            int c = e >> 6, q = e & 63;
            int hw = hw00 + ((q>>3)<<7) + (q&7);
            sV[c*65+q] = vs[(size_t)c*HWSZ + hw];
        }
    }
    __syncthreads();
    t_accum(acc, sV, sSt2, c0, p0);

    size_t ub0 = (((size_t)b*CCH + c0) << 14) + (size_t)hw00 + ((size_t)pg << 7);
#pragma unroll
    for (int i = 0; i < 8; i++) {
        size_t ga = ub0 + ((size_t)i << 14);
        *(float4*)&g_dw[ga]   = make_float4(acc[i][0],acc[i][1],acc[i][2],acc[i][3]);
        *(float4*)&g_dw[ga+4] = make_float4(acc[i][4],acc[i][5],acc[i][6],acc[i][7]);
    }
}

// ---- K4: tf32 GEMM, single-buffer fragment smem, 2 CTAs/SM ----
// smem: sAf 1024 uint4 (16KB) + sBf 2048 uint2 (16KB) = 32768 B (epilogue reuses)
#define GEMM_SMEM_BYTES 32768

__global__ __launch_bounds__(256, 2) void gemm_kernel(
    const float* __restrict__ Wv, const float* __restrict__ bvp,
    const float* __restrict__ img, const float* __restrict__ mask,
    const float* __restrict__ alpha_p, const float* __restrict__ beta_p)
{
    extern __shared__ unsigned sg[];
    uint4* sAf = (uint4*)sg;               // [1024]
    uint2* sBf = (uint2*)(sg + 4096);      // [2048]

    const int t = threadIdx.x, lane = t & 31, warp = t >> 5;
    const int warpM = warp >> 2, warpN = warp & 3;
    const int hwt = blockIdx.x, mt = blockIdx.y, b = blockIdx.z;
    const int n0 = hwt * 128;
    const float* U = g_dw;

    float d[4][4][4];
#pragma unroll
    for (int i=0;i<4;i++)
#pragma unroll
        for (int j=0;j<4;j++)
#pragma unroll
            for (int e=0;e<4;e++) d[i][j][e]=0.f;

    for (int kt = 0; kt < 8; kt++) {
        int kc = kt*32;
        __syncthreads();   // previous mma phase done before overwrite
#pragma unroll
        for (int s = 0; s < 4; s++) {
            int e = s*256 + t;
            int le = e & 31, fr = e >> 5;
            int ks = fr >> 3, wM = (fr >> 2) & 1, i = fr & 3;
            int m = mt*128 + wM*64 + i*16 + (le>>2);
            int k = kc + ks*8 + (le&3);
            const float* wp = &Wv[(size_t)m*256 + k];
            sAf[e] = make_uint4(__float_as_uint(wp[0]),
                                __float_as_uint(wp[8*256]),
                                __float_as_uint(wp[4]),
                                __float_as_uint(wp[8*256+4]));
        }
#pragma unroll
        for (int s = 0; s < 8; s++) {
            int e = s*256 + t;
            int le = e & 31, fr = e >> 5;
            int ks = fr >> 4, wN = (fr >> 2) & 3, j = fr & 3;
            int n = n0 + wN*32 + j*8 + (le>>2);
            int k = kc + ks*8 + (le&3);
            const float* up = &U[((size_t)(b*256 + k) << 14) + n];
            sBf[e] = make_uint2(__float_as_uint(up[0]),
                                __float_as_uint(up[4 << 14]));
        }
        __syncthreads();
#pragma unroll
        for (int ks = 0; ks < 4; ks++) {
            uint4 av[4]; uint2 bv[4];
#pragma unroll
            for (int i = 0; i < 4; i++)
                av[i] = sAf[((ks*2 + warpM)*4 + i)*32 + lane];
#pragma unroll
            for (int j = 0; j < 4; j++)
                bv[j] = sBf[((ks*4 + warpN)*4 + j)*32 + lane];
#pragma unroll
            for (int i = 0; i < 4; i++) {
                unsigned a[4] = {av[i].x, av[i].y, av[i].z, av[i].w};
#pragma unroll
                for (int j = 0; j < 4; j++) {
                    unsigned bb[2] = {bv[j].x, bv[j].y};
                    mma_tf32(d[i][j], a, bb);
                }
            }
        }
    }
    __syncthreads();   // done with fragments; reuse smem for GN reduction

    // epilogue: write fused, accumulate GN partials via smem tree
    float* red = (float*)sg;          // [2][128][16] = 4096 floats (16KB)
    float ab = __ldg(alpha_p) + __ldg(beta_p);
    int r = lane >> 2, cc = (lane & 3)*2;
    int slot = warpN*4 + (lane & 3);
#pragma unroll
    for (int i = 0; i < 4; i++) {
#pragma unroll
        for (int half = 0; half < 2; half++) {
            int ro = warpM*64 + i*16 + r + half*8;
            int o = mt*128 + ro;
            float bias = ab * __ldg(&bvp[o]);
            float s = 0.f, q = 0.f;
#pragma unroll
            for (int j = 0; j < 4; j++) {
                int nl = warpN*32 + j*8 + cc;
                size_t g = ((size_t)(b*256 + o) << 14) + n0 + nl;
                float2 iv = *(const float2*)&img[g];
                float2 mv = *(const float2*)&mask[g];
                float v0 = d[i][j][half*2+0] + bias + iv.x + mv.x;
                float v1 = d[i][j][half*2+1] + bias + iv.y + mv.y;
                *(float2*)&g_fused[g] = make_float2(v0, v1);
                s += v0 + v1; q += v0*v0 + v1*v1;
            }
            red[ro*16 + slot]        = s;
            red[2048 + ro*16 + slot] = q;
        }
    }
    __syncthreads();
    if (t < 128) {
        float s = 0.f, q = 0.f;
#pragma unroll
        for (int k = 0; k < 16; k++) { s += red[t*16+k]; q += red[2048 + t*16+k]; }
        red[4096 + t] = s; red[4224 + t] = q;
    }
    __syncthreads();
    if (t < 16) {
        float s = 0.f, q = 0.f;
#pragma unroll
        for (int k = 0; k < 8; k++) { s += red[4096 + t*8+k]; q += red[4224 + t*8+k]; }
        int g = mt*16 + t;
        int idx = ((b*32 + g)*128 + hwt)*2;
        g_psum[idx] = s; g_psum[idx+1] = q;
    }
}

// ---- K5: reduce GN partials ----
__global__ __launch_bounds__(128) void stats_kernel()
{
    int bg = blockIdx.x, t = threadIdx.x;
    float2 v = ((const float2*)g_psum)[bg*128 + t];
    float s = v.x, q = v.y;
#pragma unroll
    for (int o = 16; o; o >>= 1) {
        s += __shfl_xor_sync(0xffffffffu, s, o);
        q += __shfl_xor_sync(0xffffffffu, q, o);
    }
    __shared__ float ss[4], qs[4];
    if ((t & 31) == 0) { ss[t>>5] = s; qs[t>>5] = q; }
    __syncthreads();
    if (t == 0) {
        for (int w = 1; w < 4; w++) { s += ss[w]; q += qs[w]; }
        float inv = 1.f / 131072.f;
        float mu = s * inv;
        float var = q * inv - mu*mu;
        g_stats[bg] = make_float2(mu, rsqrtf(var + 1e-5f));
    }
}

// ---- K6: normalize ----
__global__ __launch_bounds__(1024) void norm_kernel(
    float* __restrict__ out, const float* __restrict__ gamma, const float* __restrict__ beta)
{
    int i4 = blockIdx.x*1024 + threadIdx.x;
    size_t e = (size_t)i4 << 2;
    int b = (int)(e >> 22), c = (int)(e >> 14) & 255;
    float2 st = g_stats[b*32 + (c >> 3)];
    float gsc = gamma[c] * st.y;
    float bsh = beta[c] - st.x * gsc;
    float4 f = *(const float4*)&g_fused[e];
    float4 r;
    r.x = f.x*gsc + bsh; r.y = f.y*gsc + bsh;
    r.z = f.z*gsc + bsh; r.w = f.w*gsc + bsh;
    *(float4*)&out[e] = r;
}

extern "C" void kernel_launch(void* const* d_in, const int* in_sizes, int n_in,
                              void* d_out, int out_size)
{
    const float* img    = (const float*)d_in[0];
    const float* mask   = (const float*)d_in[1];
    const float* qdw_w  = (const float*)d_in[2];
    const float* qdw_b  = (const float*)d_in[3];
    const float* kdw_w  = (const float*)d_in[4];
    const float* kdw_b  = (const float*)d_in[5];
    const float* vdw_w  = (const float*)d_in[6];
    const float* vdw_b  = (const float*)d_in[7];
    const float* qpw_w  = (const float*)d_in[8];
    const float* qpw_b  = (const float*)d_in[9];
    const float* kpw_w  = (const float*)d_in[10];
    const float* kpw_b  = (const float*)d_in[11];
    const float* vpw_w  = (const float*)d_in[12];
    const float* vpw_b  = (const float*)d_in[13];
    const float* alpha  = (const float*)d_in[14];
    const float* beta   = (const float*)d_in[15];
    const float* gn_w   = (const float*)d_in[16];
    const float* gn_b   = (const float*)d_in[17];

    cudaFuncSetAttribute(attn_kernel, cudaFuncAttributeMaxDynamicSharedMemorySize,
                         ATTN_SMEM_FLOATS * 4);
    cudaFuncSetAttribute(gemm_kernel, cudaFuncAttributeMaxDynamicSharedMemorySize,
                         GEMM_SMEM_BYTES);

    dw_kernel<<<65536, 256>>>(img, mask, qdw_w, qdw_b, kdw_w, kdw_b, vdw_w, vdw_b);
    dim3 g2(512, 4);
    pwqk_kernel<<<g2, 256>>>(qpw_w, qpw_b, kpw_w, kpw_b);
    attn_kernel<<<2048, 256, ATTN_SMEM_FLOATS * 4>>>(alpha, beta);
    dim3 g4(128, 2, 8);
    gemm_kernel<<<g4, 256, GEMM_SMEM_BYTES>>>(vpw_w, vpw_b, img, mask, alpha, beta);
    stats_kernel<<<256, 128>>>();
    norm_kernel<<<8192, 1024>>>((float*)d_out, gn_w, gn_b);
}

// round 9
// speedup vs baseline: 1.2464x; 1.0834x over previous
#include <cuda_runtime.h>
#include <cuda_bf16.h>

#define CCH 256
#define CMID 16
#define HWSZ 16384
#define NGRP 32

// ---- device scratch (no allocations) ----
// Reinterpreted as bf16: 6 dw planes [(proj*2+input)][b][c][hw] occupy bf16
// elements [0, 201326592); U (bf16, [b][hw][c]) lives at offset 201326592.
__device__ float g_dw[201326592];
__device__ float g_q[4194304];      // [input][b][m][hw]  fp32
__device__ float g_k[4194304];
__device__ float g_fused[33554432]; // [b][c][hw] fp32
__device__ float g_psum[131072];
__device__ float2 g_stats[256];

#define U_OFF 201326592

__device__ __forceinline__ unsigned pk2(float x, float y)
{
    __nv_bfloat162 h = __floats2bfloat162_rn(x, y);
    return *reinterpret_cast<unsigned*>(&h);
}

__device__ __forceinline__ void mma_bf16(float d[4], const unsigned a[4], const unsigned bb[2])
{
    asm volatile("mma.sync.aligned.m16n8k16.row.col.f32.bf16.bf16.f32 "
        "{%0,%1,%2,%3},{%4,%5,%6,%7},{%8,%9},{%0,%1,%2,%3};"
        : "+f"(d[0]),"+f"(d[1]),"+f"(d[2]),"+f"(d[3])
        : "r"(a[0]),"r"(a[1]),"r"(a[2]),"r"(a[3]),"r"(bb[0]),"r"(bb[1]));
}

// ---- K1: fused depthwise 3x3 (q,k,v), bf16 outputs ----
__global__ __launch_bounds__(256) void dw_kernel(
    const float* __restrict__ img, const float* __restrict__ mask,
    const float* __restrict__ qw, const float* __restrict__ qb,
    const float* __restrict__ kw, const float* __restrict__ kb,
    const float* __restrict__ vw, const float* __restrict__ vb)
{
    int bid = blockIdx.x;
    int band = bid & 15;
    int bc = (bid >> 4) & 2047;
    int input = bid >> 15;
    int c = bc & 255;
    const float* src = (input ? mask : img) + (size_t)bc * HWSZ;

    __shared__ float s[10 * 132];
    int t = threadIdx.x;
    int y0 = band * 8;
    for (int i = t; i < 10 * 130; i += 256) {
        int r = i / 130, cc = i - r * 130;
        int gy = y0 - 1 + r, gx = cc - 1;
        float v = 0.f;
        if ((unsigned)gy < 128u && (unsigned)gx < 128u) v = src[gy * 128 + gx];
        s[r * 132 + cc] = v;
    }
    float wq[9], wk[9], wv[9];
#pragma unroll
    for (int j = 0; j < 9; j++) { wq[j]=qw[c*9+j]; wk[j]=kw[c*9+j]; wv[j]=vw[c*9+j]; }
    float bq = qb[c], bk = kb[c], bv = vb[c];
    __syncthreads();

    int x = t & 127, quad = t >> 7;
    float aq[4], ak[4], av[4];
#pragma unroll
    for (int r = 0; r < 4; r++) { aq[r]=bq; ak[r]=bk; av[r]=bv; }
#pragma unroll
    for (int dx = 0; dx < 3; dx++) {
        float col[6];
#pragma unroll
        for (int rr = 0; rr < 6; rr++) col[rr] = s[(quad*4+rr)*132 + x + dx];
#pragma unroll
        for (int r = 0; r < 4; r++)
#pragma unroll
            for (int dy = 0; dy < 3; dy++) {
                float v = col[r + dy]; int j = dy*3 + dx;
                aq[r] += wq[j]*v; ak[r] += wk[j]*v; av[r] += wv[j]*v;
            }
    }
    __nv_bfloat16* gdw = (__nv_bfloat16*)g_dw;
    __nv_bfloat16* dq = gdw + ((size_t)(0 + input)*2048 + bc)*(size_t)HWSZ;
    __nv_bfloat16* dk = gdw + ((size_t)(2 + input)*2048 + bc)*(size_t)HWSZ;
    __nv_bfloat16* dv = gdw + ((size_t)(4 + input)*2048 + bc)*(size_t)HWSZ;
#pragma unroll
    for (int r = 0; r < 4; r++) {
        int y = y0 + quad*4 + r;
        dq[y*128 + x] = __float2bfloat16(aq[r]);
        dk[y*128 + x] = __float2bfloat16(ak[r]);
        dv[y*128 + x] = __float2bfloat16(av[r]);
    }
}

// ---- K2: q/k pointwise, bf16 inputs ----
__global__ __launch_bounds__(256) void pwqk_kernel(
    const float* __restrict__ qpw_w, const float* __restrict__ qpw_b,
    const float* __restrict__ kpw_w, const float* __restrict__ kpw_b)
{
    int which = blockIdx.y;
    int input = which & 1, proj = which >> 1;
    const float* Wp = proj ? kpw_w : qpw_w;
    const float* bp = proj ? kpw_b : qpw_b;
    const __nv_bfloat16* dwb = ((const __nv_bfloat16*)g_dw)
                               + (size_t)(proj*2 + input)*2048*(size_t)HWSZ;
    float* outb = (proj ? g_k : g_q) + (size_t)input*8*CMID*HWSZ;

    __shared__ float4 ws[CMID*64];
    __shared__ float  bs[CMID];
    int t = threadIdx.x;
    for (int i = t; i < CMID*64; i += 256) ws[i] = ((const float4*)Wp)[i];
    if (t < CMID) bs[t] = bp[t];
    __syncthreads();

    int n = blockIdx.x*256 + t;
    int b = n >> 14, hw = n & 16383;
    const __nv_bfloat16* xp = dwb + ((size_t)b*CCH)*HWSZ + hw;
    float acc[CMID];
#pragma unroll
    for (int m = 0; m < CMID; m++) acc[m] = bs[m];
#pragma unroll 4
    for (int c4 = 0; c4 < 64; c4++) {
        float x0 = __bfloat162float(xp[(size_t)(4*c4+0)*HWSZ]);
        float x1 = __bfloat162float(xp[(size_t)(4*c4+1)*HWSZ]);
        float x2 = __bfloat162float(xp[(size_t)(4*c4+2)*HWSZ]);
        float x3 = __bfloat162float(xp[(size_t)(4*c4+3)*HWSZ]);
#pragma unroll
        for (int m = 0; m < CMID; m++) {
            float4 w = ws[m*64 + c4];
            acc[m] += w.x*x0 + w.y*x1 + w.z*x2 + w.w*x3;
        }
    }
    float* op = outb + ((size_t)b*CMID)*HWSZ + hw;
#pragma unroll
    for (int m = 0; m < CMID; m++) op[(size_t)m*HWSZ] = acc[m];
}

// ---- K3 helpers ----
__device__ __forceinline__ void qk_gemm(const float* sQ, const float* sK, float* sSt, int t)
{
    int tx = t & 15, ty = t >> 4;
    int q0 = tx*4, p0 = ty*4;
    float a[4][4];
#pragma unroll
    for (int i=0;i<4;i++)
#pragma unroll
        for (int j=0;j<4;j++) a[i][j]=0.f;
#pragma unroll
    for (int c = 0; c < 16; c++) {
        float4 kk = *(const float4*)&sK[c*64 + q0];
        float4 qq = *(const float4*)&sQ[c*64 + p0];
        float kr[4]={kk.x,kk.y,kk.z,kk.w}, qr[4]={qq.x,qq.y,qq.z,qq.w};
#pragma unroll
        for (int i=0;i<4;i++)
#pragma unroll
            for (int j=0;j<4;j++) a[i][j] += kr[i]*qr[j];
    }
#pragma unroll
    for (int i=0;i<4;i++)
#pragma unroll
        for (int j=0;j<4;j++) sSt[(q0+i)*68 + p0+j] = 0.25f*a[i][j];
}

__device__ __forceinline__ void softmax_col(float* sSt, int p, float scale)
{
    float mx = -1e30f;
    for (int q = 0; q < 64; q++) mx = fmaxf(mx, sSt[q*68+p]);
    float sum = 0.f;
    for (int q = 0; q < 64; q++) { float e = __expf(sSt[q*68+p]-mx); sSt[q*68+p]=e; sum+=e; }
    float inv = scale / sum;
    for (int q = 0; q < 64; q++) sSt[q*68+p] *= inv;
}

__device__ __forceinline__ void t_accum(float acc[8][8], const float* sV, const float* sSt,
                                        int c0, int p0)
{
#pragma unroll 2
    for (int q = 0; q < 64; q++) {
        float av[8];
#pragma unroll
        for (int i=0;i<8;i++) av[i] = sV[(c0+i)*65 + q];
        float4 u0 = *(const float4*)&sSt[q*68 + p0];
        float4 u1 = *(const float4*)&sSt[q*68 + p0 + 4];
        float uu[8]={u0.x,u0.y,u0.z,u0.w,u1.x,u1.y,u1.z,u1.w};
#pragma unroll
        for (int i=0;i<8;i++)
#pragma unroll
            for (int j=0;j<8;j++) acc[i][j] += av[i]*uu[j];
    }
}

// smem (floats): Q 0..1024, K 1024..2048, St1 2048(4352), St2 6400(4352), V 10752(16640)
#define ATTN_SMEM_FLOATS 27392

// ---- K3: attention both directions, writes U bf16 [b][hw][c] ----
__global__ __launch_bounds__(256, 2) void attn_kernel(
    const float* __restrict__ alpha_p, const float* __restrict__ beta_p)
{
    extern __shared__ float sm[];
    float* sQ   = sm;
    float* sK   = sm + 1024;
    float* sSt1 = sm + 2048;
    float* sSt2 = sm + 6400;
    float* sV   = sm + 10752;

    int t = threadIdx.x;
    int bid = blockIdx.x;
    int b = bid >> 8, blkid = bid & 255;
    int by = blkid >> 4, bx = blkid & 15;
    float al = __ldg(alpha_p), be = __ldg(beta_p);
    int hw00 = by*8*128 + bx*8;
    const __nv_bfloat16* gdw = (const __nv_bfloat16*)g_dw;

    {   // dir1: Q=mask, K=img
        const float* qs = g_q + (((size_t)8 + b)*CMID)*HWSZ;
        const float* ks = g_k + (((size_t)0 + b)*CMID)*HWSZ;
        for (int e = t; e < 1024; e += 256) {
            int m = e >> 6, p = e & 63;
            int hw = hw00 + ((p>>3)<<7) + (p&7);
            sQ[m*64+p] = qs[(size_t)m*HWSZ + hw];
            sK[m*64+p] = ks[(size_t)m*HWSZ + hw];
        }
    }
    __syncthreads();
    qk_gemm(sQ, sK, sSt1, t);
    __syncthreads();
    {   // dir2 load + softmax(St1, alpha)
        const float* qs = g_q + (((size_t)0 + b)*CMID)*HWSZ;
        const float* ks = g_k + (((size_t)8 + b)*CMID)*HWSZ;
        for (int e = t; e < 1024; e += 256) {
            int m = e >> 6, p = e & 63;
            int hw = hw00 + ((p>>3)<<7) + (p&7);
            sQ[m*64+p] = qs[(size_t)m*HWSZ + hw];
            sK[m*64+p] = ks[(size_t)m*HWSZ + hw];
        }
        if (t < 64) softmax_col(sSt1, t, al);
    }
    __syncthreads();
    qk_gemm(sQ, sK, sSt2, t);
    __syncthreads();
    {   // load dwv(img) bf16 + softmax(St2, beta)
        const __nv_bfloat16* vs = gdw + (((size_t)4*8 + b)*CCH)*(size_t)HWSZ;
        for (int e = t; e < 256*64; e += 256) {
            int c = e >> 6, q = e & 63;
            int hw = hw00 + ((q>>3)<<7) + (q&7);
            sV[c*65+q] = __bfloat162float(vs[(size_t)c*HWSZ + hw]);
        }
        if (t < 64) softmax_col(sSt2, t, be);
    }
    __syncthreads();

    int pg = t & 7, cg = t >> 3;
    int c0 = cg*8, p0 = pg*8;
    float acc[8][8];
#pragma unroll
    for (int i=0;i<8;i++)
#pragma unroll
        for (int j=0;j<8;j++) acc[i][j]=0.f;

    t_accum(acc, sV, sSt1, c0, p0);
    __syncthreads();
    {
        const __nv_bfloat16* vs = gdw + (((size_t)5*8 + b)*CCH)*(size_t)HWSZ;
        for (int e = t; e < 256*64; e += 256) {
            int c = e >> 6, q = e & 63;
            int hw = hw00 + ((q>>3)<<7) + (q&7);
            sV[c*65+q] = __bfloat162float(vs[(size_t)c*HWSZ + hw]);
        }
    }
    __syncthreads();
    t_accum(acc, sV, sSt2, c0, p0);

    // store U bf16, layout [b][hw][c]: pixels p0..p0+7 are hw00+pg*128+j
    __nv_bfloat16* Ub = ((__nv_bfloat16*)g_dw) + U_OFF;
    size_t ub = ((size_t)b*HWSZ + (size_t)hw00 + (size_t)pg*128)*256 + c0;
#pragma unroll
    for (int j = 0; j < 8; j++) {
        uint4 pkt = make_uint4(pk2(acc[0][j], acc[1][j]), pk2(acc[2][j], acc[3][j]),
                               pk2(acc[4][j], acc[5][j]), pk2(acc[6][j], acc[7][j]));
        *(uint4*)&Ub[ub + (size_t)j*256] = pkt;
    }
}

// ---- K4: bf16 GEMM, fragment-order smem, 2 CTAs/SM ----
// smem: sAf 1024 uint4 (16KB, K-slab 64) + sBf 2048 uint2 (16KB)
#define GEMM_SMEM_BYTES 32768

__global__ __launch_bounds__(256, 2) void gemm_kernel(
    const float* __restrict__ Wv, const float* __restrict__ bvp,
    const float* __restrict__ img, const float* __restrict__ mask,
    const float* __restrict__ alpha_p, const float* __restrict__ beta_p)
{
    extern __shared__ unsigned sg[];
    uint4* sAf = (uint4*)sg;               // [1024]
    uint2* sBf = (uint2*)(sg + 4096);      // [2048]
    const __nv_bfloat16* Ub = ((const __nv_bfloat16*)g_dw) + U_OFF;

    const int t = threadIdx.x, lane = t & 31, warp = t >> 5;
    const int warpM = warp >> 2, warpN = warp & 3;
    const int hwt = blockIdx.x, mt = blockIdx.y, b = blockIdx.z;
    const int n0 = hwt * 128;

    float d[4][4][4];
#pragma unroll
    for (int i=0;i<4;i++)
#pragma unroll
        for (int j=0;j<4;j++)
#pragma unroll
            for (int e=0;e<4;e++) d[i][j][e]=0.f;

    for (int kt = 0; kt < 4; kt++) {       // K slabs of 64
        int kc = kt*64;
        __syncthreads();
        // A fill: entry fr=((ks*2+wM)*4+i), lane: rows m,(m+8); k-pairs k,(k+8)
#pragma unroll
        for (int s = 0; s < 4; s++) {
            int e = s*256 + t;
            int le = e & 31, fr = e >> 5;
            int ks = fr >> 3, wM = (fr >> 2) & 1, i = fr & 3;
            int m = mt*128 + wM*64 + i*16 + (le>>2);
            int k = kc + ks*16 + 2*(le&3);
            const float* wp = &Wv[(size_t)m*256 + k];
            sAf[e] = make_uint4(pk2(wp[0],       wp[1]),
                                pk2(wp[8*256],   wp[8*256+1]),
                                pk2(wp[8],       wp[9]),
                                pk2(wp[8*256+8], wp[8*256+9]));
        }
        // B fill: entry fr=((ks*4+wN)*4+j); uint2 = {U[n][k..k+1], U[n][k+8..k+9]}
#pragma unroll
        for (int s = 0; s < 8; s++) {
            int e = s*256 + t;
            int le = e & 31, fr = e >> 5;
            int ks = fr >> 4, wN = (fr >> 2) & 3, j = fr & 3;
            int n = n0 + wN*32 + j*8 + (le>>2);
            int k = kc + ks*16 + 2*(le&3);
            const __nv_bfloat16* up = &Ub[((size_t)b*HWSZ + n)*256 + k];
            sBf[e] = make_uint2(*(const unsigned*)up, *(const unsigned*)(up + 8));
        }
        __syncthreads();
#pragma unroll
        for (int ks = 0; ks < 4; ks++) {
            uint4 av[4]; uint2 bv[4];
#pragma unroll
            for (int i = 0; i < 4; i++)
                av[i] = sAf[((ks*2 + warpM)*4 + i)*32 + lane];
#pragma unroll
            for (int j = 0; j < 4; j++)
                bv[j] = sBf[((ks*4 + warpN)*4 + j)*32 + lane];
#pragma unroll
            for (int i = 0; i < 4; i++) {
                unsigned a[4] = {av[i].x, av[i].y, av[i].z, av[i].w};
#pragma unroll
                for (int j = 0; j < 4; j++) {
                    unsigned bb[2] = {bv[j].x, bv[j].y};
                    mma_bf16(d[i][j], a, bb);
                }
            }
        }
    }
    __syncthreads();   // reuse smem for GN reduction

    float* red = (float*)sg;
    float ab = __ldg(alpha_p) + __ldg(beta_p);
    int r = lane >> 2, cc = (lane & 3)*2;
    int slot = warpN*4 + (lane & 3);
#pragma unroll
    for (int i = 0; i < 4; i++) {
#pragma unroll
        for (int half = 0; half < 2; half++) {
            int ro = warpM*64 + i*16 + r + half*8;
            int o = mt*128 + ro;
            float bias = ab * __ldg(&bvp[o]);
            float s = 0.f, q = 0.f;
#pragma unroll
            for (int j = 0; j < 4; j++) {
                int nl = warpN*32 + j*8 + cc;
                size_t g = ((size_t)(b*256 + o) << 14) + n0 + nl;
                float2 iv = *(const float2*)&img[g];
                float2 mv = *(const float2*)&mask[g];
                float v0 = d[i][j][half*2+0] + bias + iv.x + mv.x;
                float v1 = d[i][j][half*2+1] + bias + iv.y + mv.y;
                *(float2*)&g_fused[g] = make_float2(v0, v1);
                s += v0 + v1; q += v0*v0 + v1*v1;
            }
            red[ro*16 + slot]        = s;
            red[2048 + ro*16 + slot] = q;
        }
    }
    __syncthreads();
    if (t < 128) {
        float s = 0.f, q = 0.f;
#pragma unroll
        for (int k = 0; k < 16; k++) { s += red[t*16+k]; q += red[2048 + t*16+k]; }
        red[4096 + t] = s; red[4224 + t] = q;
    }
    __syncthreads();
    if (t < 16) {
        float s = 0.f, q = 0.f;
#pragma unroll
        for (int k = 0; k < 8; k++) { s += red[4096 + t*8+k]; q += red[4224 + t*8+k]; }
        int g = mt*16 + t;
        int idx = ((b*32 + g)*128 + hwt)*2;
        g_psum[idx] = s; g_psum[idx+1] = q;
    }
}

// ---- K5: reduce GN partials ----
__global__ __launch_bounds__(128) void stats_kernel()
{
    int bg = blockIdx.x, t = threadIdx.x;
    float2 v = ((const float2*)g_psum)[bg*128 + t];
    float s = v.x, q = v.y;
#pragma unroll
    for (int o = 16; o; o >>= 1) {
        s += __shfl_xor_sync(0xffffffffu, s, o);
        q += __shfl_xor_sync(0xffffffffu, q, o);
    }
    __shared__ float ss[4], qs[4];
    if ((t & 31) == 0) { ss[t>>5] = s; qs[t>>5] = q; }
    __syncthreads();
    if (t == 0) {
        for (int w = 1; w < 4; w++) { s += ss[w]; q += qs[w]; }
        float inv = 1.f / 131072.f;
        float mu = s * inv;
        float var = q * inv - mu*mu;
        g_stats[bg] = make_float2(mu, rsqrtf(var + 1e-5f));
    }
}

// ---- K6: normalize ----
__global__ __launch_bounds__(1024) void norm_kernel(
    float* __restrict__ out, const float* __restrict__ gamma, const float* __restrict__ beta)
{
    int i4 = blockIdx.x*1024 + threadIdx.x;
    size_t e = (size_t)i4 << 2;
    int b = (int)(e >> 22), c = (int)(e >> 14) & 255;
    float2 st = g_stats[b*32 + (c >> 3)];
    float gsc = gamma[c] * st.y;
    float bsh = beta[c] - st.x * gsc;
    float4 f = *(const float4*)&g_fused[e];
    float4 r;
    r.x = f.x*gsc + bsh; r.y = f.y*gsc + bsh;
    r.z = f.z*gsc + bsh; r.w = f.w*gsc + bsh;
    *(float4*)&out[e] = r;
}

extern "C" void kernel_launch(void* const* d_in, const int* in_sizes, int n_in,
                              void* d_out, int out_size)
{
    const float* img    = (const float*)d_in[0];
    const float* mask   = (const float*)d_in[1];
    const float* qdw_w  = (const float*)d_in[2];
    const float* qdw_b  = (const float*)d_in[3];
    const float* kdw_w  = (const float*)d_in[4];
    const float* kdw_b  = (const float*)d_in[5];
    const float* vdw_w  = (const float*)d_in[6];
    const float* vdw_b  = (const float*)d_in[7];
    const float* qpw_w  = (const float*)d_in[8];
    const float* qpw_b  = (const float*)d_in[9];
    const float* kpw_w  = (const float*)d_in[10];
    const float* kpw_b  = (const float*)d_in[11];
    const float* vpw_w  = (const float*)d_in[12];
    const float* vpw_b  = (const float*)d_in[13];
    const float* alpha  = (const float*)d_in[14];
    const float* beta   = (const float*)d_in[15];
    const float* gn_w   = (const float*)d_in[16];
    const float* gn_b   = (const float*)d_in[17];

    cudaFuncSetAttribute(attn_kernel, cudaFuncAttributeMaxDynamicSharedMemorySize,
                         ATTN_SMEM_FLOATS * 4);
    cudaFuncSetAttribute(gemm_kernel, cudaFuncAttributeMaxDynamicSharedMemorySize,
                         GEMM_SMEM_BYTES);

    dw_kernel<<<65536, 256>>>(img, mask, qdw_w, qdw_b, kdw_w, kdw_b, vdw_w, vdw_b);
    dim3 g2(512, 4);
    pwqk_kernel<<<g2, 256>>>(qpw_w, qpw_b, kpw_w, kpw_b);
    attn_kernel<<<2048, 256, ATTN_SMEM_FLOATS * 4>>>(alpha, beta);
    dim3 g4(128, 2, 8);
    gemm_kernel<<<g4, 256, GEMM_SMEM_BYTES>>>(vpw_w, vpw_b, img, mask, alpha, beta);
    stats_kernel<<<256, 128>>>();
    norm_kernel<<<8192, 1024>>>((float*)d_out, gn_w, gn_b);
}